// round 1
// baseline (speedup 1.0000x reference)
#include <cuda_runtime.h>

#define TSEQ   2048
#define DMODEL 1024
#define NHEADS 16
#define DKH    64
#define NBATCH 4
#define NROWS  (NBATCH * TSEQ)   // 8192

// Scratch: head-major Q/K/V [(b*H + h)*T + t]*64 + d, and ctx [B,T,DMODEL]
__device__ float g_q[(size_t)NBATCH * NHEADS * TSEQ * DKH];
__device__ float g_k[(size_t)NBATCH * NHEADS * TSEQ * DKH];
__device__ float g_v[(size_t)NBATCH * NHEADS * TSEQ * DKH];
__device__ float g_ctx[(size_t)NROWS * DMODEL];

// ---------------------------------------------------------------------------
// GEMM: C[M,N] = A[M,K] @ W[K,N] + bias.  M=8192, N=K=1024.
// 128x128 block tile, K-tile 8, 256 threads, 8x8 per-thread.
// HEADS_OUT=1 scatters output to head-major [(b*H+h)*T+t]*64+d layout.
// ---------------------------------------------------------------------------
template <int HEADS_OUT>
__global__ __launch_bounds__(256) void gemm_kernel(
    const float* __restrict__ A, const float* __restrict__ W,
    const float* __restrict__ bias, float* __restrict__ C)
{
    __shared__ float As[8][128];   // k-major: As[k][m]
    __shared__ float Ws[8][128];   // Ws[k][n]

    const int tid = threadIdx.x;
    const int m0 = blockIdx.y * 128;
    const int n0 = blockIdx.x * 128;
    const int tm = tid >> 4, tn = tid & 15;

    const int la_row = tid >> 1;          // 0..127
    const int la_k   = (tid & 1) << 2;    // 0 or 4
    const int lw_k   = tid >> 5;          // 0..7
    const int lw_col = (tid & 31) << 2;   // 0..124

    float acc[8][8];
#pragma unroll
    for (int i = 0; i < 8; i++)
#pragma unroll
        for (int j = 0; j < 8; j++) acc[i][j] = 0.f;

    const float* Aptr = A + (size_t)(m0 + la_row) * DMODEL + la_k;
    const float* Wptr = W + (size_t)lw_k * DMODEL + n0 + lw_col;

    for (int k0 = 0; k0 < DMODEL; k0 += 8) {
        float4 a4 = *(const float4*)(Aptr + k0);
        float4 w4 = *(const float4*)(Wptr + (size_t)k0 * DMODEL);
        __syncthreads();
        As[la_k + 0][la_row] = a4.x;
        As[la_k + 1][la_row] = a4.y;
        As[la_k + 2][la_row] = a4.z;
        As[la_k + 3][la_row] = a4.w;
        *(float4*)&Ws[lw_k][lw_col] = w4;
        __syncthreads();
#pragma unroll
        for (int kk = 0; kk < 8; kk++) {
            float a[8], b[8];
            *(float4*)(a)     = *(float4*)&As[kk][tm * 8];
            *(float4*)(a + 4) = *(float4*)&As[kk][tm * 8 + 4];
            *(float4*)(b)     = *(float4*)&Ws[kk][tn * 8];
            *(float4*)(b + 4) = *(float4*)&Ws[kk][tn * 8 + 4];
#pragma unroll
            for (int i = 0; i < 8; i++)
#pragma unroll
                for (int j = 0; j < 8; j++)
                    acc[i][j] += a[i] * b[j];
        }
    }

#pragma unroll
    for (int i = 0; i < 8; i++) {
        const int m = m0 + tm * 8 + i;
        const int b = m >> 11;            // /TSEQ
        const int t = m & (TSEQ - 1);
#pragma unroll
        for (int j = 0; j < 8; j++) {
            const int n = n0 + tn * 8 + j;
            const float v = acc[i][j] + bias[n];
            if (HEADS_OUT) {
                const int h = n >> 6, d = n & 63;
                C[(((size_t)(b * NHEADS + h) * TSEQ + t) << 6) + d] = v;
            } else {
                C[(size_t)m * DMODEL + n] = v;
            }
        }
    }
}

// ---------------------------------------------------------------------------
// Flash attention, fp32. One block = one (b,h) x 128-query tile.
// Iterates key tiles of 64, online softmax. 256 threads, 8x4 per-thread.
// Q,K stored d-major in smem so compute-phase LDS are conflict-free float4.
// ---------------------------------------------------------------------------
#define SMEM_FLOATS (64 * 128 + 64 * 64 + 64 * 68 + 128 * 68)  // 25344
#define SMEM_BYTES  (SMEM_FLOATS * 4)                          // 101376

__global__ __launch_bounds__(256, 1) void attn_kernel(
    const float* __restrict__ Q, const float* __restrict__ K,
    const float* __restrict__ V, float* __restrict__ ctx)
{
    extern __shared__ float sm[];
    float* Qs = sm;                  // [64 d][128 r]
    float* Ks = Qs + 64 * 128;       // [64 d][64 c]
    float* Vs = Ks + 64 * 64;        // [64 j][68 d]
    float* Ps = Vs + 64 * 68;        // [128 i][68 j]

    const int tid = threadIdx.x;
    const int tx = tid & 15, ty = tid >> 4;
    const int r0 = ty * 8, c0 = tx * 4;
    const int bh = blockIdx.y;
    const int q0 = blockIdx.x * 128;

    const float* Qg = Q + (size_t)bh * TSEQ * DKH;
    const float* Kg = K + (size_t)bh * TSEQ * DKH;
    const float* Vg = V + (size_t)bh * TSEQ * DKH;

    // Load Q tile transposed (d-major)
    for (int idx = tid; idx < 128 * 16; idx += 256) {
        const int r = idx & 127, d4 = idx >> 7;
        float4 q4 = *(const float4*)&Qg[(size_t)(q0 + r) * DKH + d4 * 4];
        Qs[(d4 * 4 + 0) * 128 + r] = q4.x;
        Qs[(d4 * 4 + 1) * 128 + r] = q4.y;
        Qs[(d4 * 4 + 2) * 128 + r] = q4.z;
        Qs[(d4 * 4 + 3) * 128 + r] = q4.w;
    }

    float m_i[8], l_i[8], O[8][4];
#pragma unroll
    for (int i = 0; i < 8; i++) {
        m_i[i] = -1e30f; l_i[i] = 0.f;
#pragma unroll
        for (int d = 0; d < 4; d++) O[i][d] = 0.f;
    }

    for (int kt = 0; kt < TSEQ / 64; kt++) {
        __syncthreads();  // prior iter's Ps/Vs reads done
        // K tile, transposed (d-major)
        for (int idx = tid; idx < 64 * 16; idx += 256) {
            const int c = idx & 63, d4 = idx >> 6;
            float4 k4 = *(const float4*)&Kg[(size_t)(kt * 64 + c) * DKH + d4 * 4];
            Ks[(d4 * 4 + 0) * 64 + c] = k4.x;
            Ks[(d4 * 4 + 1) * 64 + c] = k4.y;
            Ks[(d4 * 4 + 2) * 64 + c] = k4.z;
            Ks[(d4 * 4 + 3) * 64 + c] = k4.w;
        }
        // V tile, row-major
        for (int idx = tid; idx < 64 * 16; idx += 256) {
            const int j = idx >> 4, c4 = idx & 15;
            *(float4*)&Vs[j * 68 + c4 * 4] =
                *(const float4*)&Vg[(size_t)(kt * 64 + j) * DKH + c4 * 4];
        }
        __syncthreads();

        // S = Q K^T  (per-thread 8x4)
        float s[8][4];
#pragma unroll
        for (int i = 0; i < 8; i++)
#pragma unroll
            for (int j = 0; j < 4; j++) s[i][j] = 0.f;

#pragma unroll 8
        for (int d = 0; d < 64; d++) {
            float4 k4 = *(float4*)&Ks[d * 64 + c0];
            float4 qa = *(float4*)&Qs[d * 128 + r0];
            float4 qb = *(float4*)&Qs[d * 128 + r0 + 4];
            const float q[8] = {qa.x, qa.y, qa.z, qa.w, qb.x, qb.y, qb.z, qb.w};
            const float k[4] = {k4.x, k4.y, k4.z, k4.w};
#pragma unroll
            for (int rr = 0; rr < 8; rr++)
#pragma unroll
                for (int cc = 0; cc < 4; cc++)
                    s[rr][cc] += q[rr] * k[cc];
        }

        // Online softmax (rows owned by 16-lane groups; xor<16 stays in-group)
#pragma unroll
        for (int rr = 0; rr < 8; rr++) {
#pragma unroll
            for (int cc = 0; cc < 4; cc++) s[rr][cc] *= 0.125f;  // 1/sqrt(64)
            float mt = fmaxf(fmaxf(s[rr][0], s[rr][1]), fmaxf(s[rr][2], s[rr][3]));
#pragma unroll
            for (int o = 8; o; o >>= 1)
                mt = fmaxf(mt, __shfl_xor_sync(0xffffffffu, mt, o));
            const float mnew = fmaxf(m_i[rr], mt);
            const float corr = __expf(m_i[rr] - mnew);
            m_i[rr] = mnew;
            float rs = 0.f;
#pragma unroll
            for (int cc = 0; cc < 4; cc++) {
                const float p = __expf(s[rr][cc] - mnew);
                s[rr][cc] = p;
                rs += p;
            }
#pragma unroll
            for (int o = 8; o; o >>= 1)
                rs += __shfl_xor_sync(0xffffffffu, rs, o);
            l_i[rr] = l_i[rr] * corr + rs;
#pragma unroll
            for (int dd = 0; dd < 4; dd++) O[rr][dd] *= corr;
            *(float4*)&Ps[(r0 + rr) * 68 + c0] =
                make_float4(s[rr][0], s[rr][1], s[rr][2], s[rr][3]);
        }
        __syncthreads();

        // O += P V
#pragma unroll 4
        for (int j = 0; j < 64; j++) {
            float4 v4 = *(float4*)&Vs[j * 68 + c0];
            float pj[8];
#pragma unroll
            for (int rr = 0; rr < 8; rr++) pj[rr] = Ps[(r0 + rr) * 68 + j];
#pragma unroll
            for (int rr = 0; rr < 8; rr++) {
                O[rr][0] += pj[rr] * v4.x;
                O[rr][1] += pj[rr] * v4.y;
                O[rr][2] += pj[rr] * v4.z;
                O[rr][3] += pj[rr] * v4.w;
            }
        }
    }

    // Normalize and write ctx in [B, T, DMODEL] layout
    const int b = bh >> 4, h = bh & 15;
#pragma unroll
    for (int rr = 0; rr < 8; rr++) {
        const float inv = 1.f / l_i[rr];
        const int t = q0 + r0 + rr;
        float4 o4 = make_float4(O[rr][0] * inv, O[rr][1] * inv,
                                O[rr][2] * inv, O[rr][3] * inv);
        *(float4*)&ctx[((size_t)(b * TSEQ + t)) * DMODEL + h * 64 + c0] = o4;
    }
}

// ---------------------------------------------------------------------------
extern "C" void kernel_launch(void* const* d_in, const int* in_sizes, int n_in,
                              void* d_out, int out_size)
{
    const float* query = (const float*)d_in[0];
    const float* key   = (const float*)d_in[1];
    const float* value = (const float*)d_in[2];
    const float* Wq = (const float*)d_in[3];
    const float* bq = (const float*)d_in[4];
    const float* Wk = (const float*)d_in[5];
    const float* bk = (const float*)d_in[6];
    const float* Wv = (const float*)d_in[7];
    const float* bv = (const float*)d_in[8];
    const float* Wo = (const float*)d_in[9];
    const float* bo = (const float*)d_in[10];
    float* out = (float*)d_out;

    float *qp, *kp, *vp, *cp;
    cudaGetSymbolAddress((void**)&qp, g_q);
    cudaGetSymbolAddress((void**)&kp, g_k);
    cudaGetSymbolAddress((void**)&vp, g_v);
    cudaGetSymbolAddress((void**)&cp, g_ctx);

    cudaFuncSetAttribute(attn_kernel,
                         cudaFuncAttributeMaxDynamicSharedMemorySize, SMEM_BYTES);

    const dim3 gg(DMODEL / 128, NROWS / 128);   // (8, 64)
    gemm_kernel<1><<<gg, 256>>>(query, Wq, bq, qp);
    gemm_kernel<1><<<gg, 256>>>(key,   Wk, bk, kp);
    gemm_kernel<1><<<gg, 256>>>(value, Wv, bv, vp);
    attn_kernel<<<dim3(TSEQ / 128, NBATCH * NHEADS), 256, SMEM_BYTES>>>(qp, kp, vp, cp);
    gemm_kernel<0><<<gg, 256>>>(cp, Wo, bo, out);
}

// round 3
// speedup vs baseline: 1.0989x; 1.0989x over previous
#include <cuda_runtime.h>
#include <cstdint>

#define TSEQ   2048
#define DMODEL 1024
#define NHEADS 16
#define DKH    64
#define NBATCH 4
#define NROWS  (NBATCH * TSEQ)   // 8192

// Scratch
__device__ float g_q[(size_t)NBATCH * NHEADS * TSEQ * DKH];
__device__ float g_k[(size_t)NBATCH * NHEADS * TSEQ * DKH];
__device__ float g_v[(size_t)NBATCH * NHEADS * TSEQ * DKH];
__device__ float g_ctx[(size_t)NROWS * DMODEL];

// ---------------------------------------------------------------------------
static __device__ __forceinline__ float tf32r(float x) {
    uint32_t u;
    asm("cvt.rna.tf32.f32 %0, %1;" : "=r"(u) : "f"(x));
    return __uint_as_float(u);
}

static __device__ __forceinline__ void mma1688(float* d, const uint32_t* a,
                                               const uint32_t* b) {
    asm volatile(
        "mma.sync.aligned.m16n8k8.row.col.f32.tf32.tf32.f32 "
        "{%0,%1,%2,%3}, {%4,%5,%6,%7}, {%8,%9}, {%0,%1,%2,%3};"
        : "+f"(d[0]), "+f"(d[1]), "+f"(d[2]), "+f"(d[3])
        : "r"(a[0]), "r"(a[1]), "r"(a[2]), "r"(a[3]), "r"(b[0]), "r"(b[1]));
}

// ---------------------------------------------------------------------------
// tf32 mma.sync GEMM: C[M,N] = A[M,K] @ W[K,N] + bias.  M=8192, N=K=1024.
// CTA 128x128, BK=16, 256 threads. Warp tile 64x32 (warp_m=wid&1, warp_n=wid>>1).
// Smem in fragment-permuted layout: compute loads are conflict-free LDS.128.
//   A slot: [kstep][mt16][lane][reg], lane=4*(m%8)+(k%4), reg=((m%16)>>3)+2*((k%8)>>2)
//   B slot: [kstep][nt16][lane][reg], lane=4*(n%8)+(k%4), reg=2*((n%16)>>3)+((k%8)>>2)
// ---------------------------------------------------------------------------
template <int HEADS_OUT>
__global__ __launch_bounds__(256, 1) void gemm_mma(
    const float* __restrict__ A, const float* __restrict__ W,
    const float* __restrict__ bias, float* __restrict__ C)
{
    __shared__ float sA[2][2048];
    __shared__ float sB[2][2048];

    const int tid = threadIdx.x;
    const int lane = tid & 31, wid = tid >> 5;
    const int warp_m = wid & 1, warp_n = wid >> 1;
    const int n0 = blockIdx.x * 128, m0 = blockIdx.y * 128;

    // Loader indices (2 float4 each for A and B per chunk)
    // A: flat = l*256+tid -> m=flat>>2 (0..127), g=flat&3 (k=4g..4g+3)
    // B: flat -> k_local=flat>>5 (0..15), ng=flat&31 (n=4*ng..4*ng+3)
    float4 aR[2], bR[2];
    const float* Ap[2];
    const float* Wp[2];
#pragma unroll
    for (int l = 0; l < 2; l++) {
        const int fl = l * 256 + tid;
        Ap[l] = A + (size_t)(m0 + (fl >> 2)) * DMODEL + ((fl & 3) << 2);
        Wp[l] = W + (size_t)(fl >> 5) * DMODEL + n0 + ((fl & 31) << 2);
    }

    float acc[4][4][4];
#pragma unroll
    for (int i = 0; i < 4; i++)
#pragma unroll
        for (int j = 0; j < 4; j++)
#pragma unroll
            for (int r = 0; r < 4; r++) acc[i][j][r] = 0.f;

    // Prefetch chunk 0
#pragma unroll
    for (int l = 0; l < 2; l++) {
        aR[l] = *(const float4*)(Ap[l]);
        bR[l] = *(const float4*)(Wp[l]);
    }

    for (int c = 0; c < DMODEL / 16; ++c) {
        const int s = c & 1;
        // --- scatter-store regs into fragment layout ---
#pragma unroll
        for (int l = 0; l < 2; l++) {
            const int fl = l * 256 + tid;
            {   // A
                const int m = fl >> 2, g = fl & 3;
                const int ks = g >> 1, kh = g & 1, mt = m >> 4;
                const int reg = ((m >> 3) & 1) + 2 * kh;
                float* base = &sA[s][(((ks * 8 + mt) * 32) << 2) + reg];
                const float v[4] = {aR[l].x, aR[l].y, aR[l].z, aR[l].w};
#pragma unroll
                for (int j = 0; j < 4; j++)
                    base[(4 * (m & 7) + j) << 2] = tf32r(v[j]);
            }
            {   // B
                const int kl = fl >> 5, ng = fl & 31;
                const int ks = kl >> 3, kh = (kl >> 2) & 1, nt = ng >> 2;
                const int reg = 2 * ((ng >> 1) & 1) + kh;
                float* base = &sB[s][(((ks * 8 + nt) * 32) << 2) + reg];
                const float v[4] = {bR[l].x, bR[l].y, bR[l].z, bR[l].w};
#pragma unroll
                for (int j = 0; j < 4; j++)
                    base[(4 * (((ng << 2) + j) & 7) + (kl & 3)) << 2] = tf32r(v[j]);
            }
        }
        __syncthreads();

        // --- prefetch next chunk ---
        if (c + 1 < DMODEL / 16) {
#pragma unroll
            for (int l = 0; l < 2; l++) {
                aR[l] = *(const float4*)(Ap[l] + (c + 1) * 16);
                bR[l] = *(const float4*)(Wp[l] + (size_t)(c + 1) * 16 * DMODEL);
            }
        }

        // --- compute 2 k8 steps ---
#pragma unroll
        for (int ks = 0; ks < 2; ks++) {
            uint32_t af[4][4], bf[2][4];
#pragma unroll
            for (int mi = 0; mi < 4; mi++)
                *(float4*)af[mi] = *(float4*)&sA[s][((ks * 8 + warp_m * 4 + mi) * 32 + lane) << 2];
#pragma unroll
            for (int nt = 0; nt < 2; nt++)
                *(float4*)bf[nt] = *(float4*)&sB[s][((ks * 8 + warp_n * 2 + nt) * 32 + lane) << 2];
#pragma unroll
            for (int mi = 0; mi < 4; mi++)
#pragma unroll
                for (int nt = 0; nt < 2; nt++) {
                    mma1688(acc[mi][nt * 2 + 0], af[mi], &bf[nt][0]);
                    mma1688(acc[mi][nt * 2 + 1], af[mi], &bf[nt][2]);
                }
        }
        __syncthreads();
    }

    // --- epilogue ---
#pragma unroll
    for (int mi = 0; mi < 4; mi++) {
#pragma unroll
        for (int nj = 0; nj < 4; nj++) {
            const int n = n0 + warp_n * 32 + nj * 8 + ((lane & 3) << 1);
            const float2 b2 = *(const float2*)(bias + n);
#pragma unroll
            for (int half = 0; half < 2; half++) {
                const int m = m0 + warp_m * 64 + mi * 16 + (lane >> 2) + half * 8;
                float2 v;
                v.x = acc[mi][nj][half * 2 + 0] + b2.x;
                v.y = acc[mi][nj][half * 2 + 1] + b2.y;
                if (HEADS_OUT) {
                    const int bb = m >> 11, t = m & (TSEQ - 1);
                    const int h = n >> 6, dd = n & 63;
                    *(float2*)(C + (((size_t)(bb * NHEADS + h) * TSEQ + t) << 6) + dd) = v;
                } else {
                    *(float2*)(C + (size_t)m * DMODEL + n) = v;
                }
            }
        }
    }
}

// ---------------------------------------------------------------------------
// Flash attention, fp32 SIMT (unchanged, known-good)
// ---------------------------------------------------------------------------
#define SMEM_FLOATS (64 * 128 + 64 * 64 + 64 * 68 + 128 * 68)
#define SMEM_BYTES  (SMEM_FLOATS * 4)

__global__ __launch_bounds__(256, 1) void attn_kernel(
    const float* __restrict__ Q, const float* __restrict__ K,
    const float* __restrict__ V, float* __restrict__ ctx)
{
    extern __shared__ float sm[];
    float* Qs = sm;
    float* Ks = Qs + 64 * 128;
    float* Vs = Ks + 64 * 64;
    float* Ps = Vs + 64 * 68;

    const int tid = threadIdx.x;
    const int tx = tid & 15, ty = tid >> 4;
    const int r0 = ty * 8, c0 = tx * 4;
    const int bh = blockIdx.y;
    const int q0 = blockIdx.x * 128;

    const float* Qg = Q + (size_t)bh * TSEQ * DKH;
    const float* Kg = K + (size_t)bh * TSEQ * DKH;
    const float* Vg = V + (size_t)bh * TSEQ * DKH;

    for (int idx = tid; idx < 128 * 16; idx += 256) {
        const int r = idx & 127, d4 = idx >> 7;
        float4 q4 = *(const float4*)&Qg[(size_t)(q0 + r) * DKH + d4 * 4];
        Qs[(d4 * 4 + 0) * 128 + r] = q4.x;
        Qs[(d4 * 4 + 1) * 128 + r] = q4.y;
        Qs[(d4 * 4 + 2) * 128 + r] = q4.z;
        Qs[(d4 * 4 + 3) * 128 + r] = q4.w;
    }

    float m_i[8], l_i[8], O[8][4];
#pragma unroll
    for (int i = 0; i < 8; i++) {
        m_i[i] = -1e30f; l_i[i] = 0.f;
#pragma unroll
        for (int d = 0; d < 4; d++) O[i][d] = 0.f;
    }

    for (int kt = 0; kt < TSEQ / 64; kt++) {
        __syncthreads();
        for (int idx = tid; idx < 64 * 16; idx += 256) {
            const int c = idx & 63, d4 = idx >> 6;
            float4 k4 = *(const float4*)&Kg[(size_t)(kt * 64 + c) * DKH + d4 * 4];
            Ks[(d4 * 4 + 0) * 64 + c] = k4.x;
            Ks[(d4 * 4 + 1) * 64 + c] = k4.y;
            Ks[(d4 * 4 + 2) * 64 + c] = k4.z;
            Ks[(d4 * 4 + 3) * 64 + c] = k4.w;
        }
        for (int idx = tid; idx < 64 * 16; idx += 256) {
            const int j = idx >> 4, c4 = idx & 15;
            *(float4*)&Vs[j * 68 + c4 * 4] =
                *(const float4*)&Vg[(size_t)(kt * 64 + j) * DKH + c4 * 4];
        }
        __syncthreads();

        float s[8][4];
#pragma unroll
        for (int i = 0; i < 8; i++)
#pragma unroll
            for (int j = 0; j < 4; j++) s[i][j] = 0.f;

#pragma unroll 8
        for (int d = 0; d < 64; d++) {
            float4 k4 = *(float4*)&Ks[d * 64 + c0];
            float4 qa = *(float4*)&Qs[d * 128 + r0];
            float4 qb = *(float4*)&Qs[d * 128 + r0 + 4];
            const float q[8] = {qa.x, qa.y, qa.z, qa.w, qb.x, qb.y, qb.z, qb.w};
            const float k[4] = {k4.x, k4.y, k4.z, k4.w};
#pragma unroll
            for (int rr = 0; rr < 8; rr++)
#pragma unroll
                for (int cc = 0; cc < 4; cc++)
                    s[rr][cc] += q[rr] * k[cc];
        }

#pragma unroll
        for (int rr = 0; rr < 8; rr++) {
#pragma unroll
            for (int cc = 0; cc < 4; cc++) s[rr][cc] *= 0.125f;
            float mt = fmaxf(fmaxf(s[rr][0], s[rr][1]), fmaxf(s[rr][2], s[rr][3]));
#pragma unroll
            for (int o = 8; o; o >>= 1)
                mt = fmaxf(mt, __shfl_xor_sync(0xffffffffu, mt, o));
            const float mnew = fmaxf(m_i[rr], mt);
            const float corr = __expf(m_i[rr] - mnew);
            m_i[rr] = mnew;
            float rs = 0.f;
#pragma unroll
            for (int cc = 0; cc < 4; cc++) {
                const float p = __expf(s[rr][cc] - mnew);
                s[rr][cc] = p;
                rs += p;
            }
#pragma unroll
            for (int o = 8; o; o >>= 1)
                rs += __shfl_xor_sync(0xffffffffu, rs, o);
            l_i[rr] = l_i[rr] * corr + rs;
#pragma unroll
            for (int dd = 0; dd < 4; dd++) O[rr][dd] *= corr;
            *(float4*)&Ps[(r0 + rr) * 68 + c0] =
                make_float4(s[rr][0], s[rr][1], s[rr][2], s[rr][3]);
        }
        __syncthreads();

#pragma unroll 4
        for (int j = 0; j < 64; j++) {
            float4 v4 = *(float4*)&Vs[j * 68 + c0];
            float pj[8];
#pragma unroll
            for (int rr = 0; rr < 8; rr++) pj[rr] = Ps[(r0 + rr) * 68 + j];
#pragma unroll
            for (int rr = 0; rr < 8; rr++) {
                O[rr][0] += pj[rr] * v4.x;
                O[rr][1] += pj[rr] * v4.y;
                O[rr][2] += pj[rr] * v4.z;
                O[rr][3] += pj[rr] * v4.w;
            }
        }
    }

    const int b = bh >> 4, h = bh & 15;
#pragma unroll
    for (int rr = 0; rr < 8; rr++) {
        const float inv = 1.f / l_i[rr];
        const int t = q0 + r0 + rr;
        float4 o4 = make_float4(O[rr][0] * inv, O[rr][1] * inv,
                                O[rr][2] * inv, O[rr][3] * inv);
        *(float4*)&ctx[((size_t)(b * TSEQ + t)) * DMODEL + h * 64 + c0] = o4;
    }
}

// ---------------------------------------------------------------------------
extern "C" void kernel_launch(void* const* d_in, const int* in_sizes, int n_in,
                              void* d_out, int out_size)
{
    const float* query = (const float*)d_in[0];
    const float* key   = (const float*)d_in[1];
    const float* value = (const float*)d_in[2];
    const float* Wq = (const float*)d_in[3];
    const float* bq = (const float*)d_in[4];
    const float* Wk = (const float*)d_in[5];
    const float* bk = (const float*)d_in[6];
    const float* Wv = (const float*)d_in[7];
    const float* bv = (const float*)d_in[8];
    const float* Wo = (const float*)d_in[9];
    const float* bo = (const float*)d_in[10];
    float* out = (float*)d_out;

    float *qp, *kp, *vp, *cp;
    cudaGetSymbolAddress((void**)&qp, g_q);
    cudaGetSymbolAddress((void**)&kp, g_k);
    cudaGetSymbolAddress((void**)&vp, g_v);
    cudaGetSymbolAddress((void**)&cp, g_ctx);

    cudaFuncSetAttribute(attn_kernel,
                         cudaFuncAttributeMaxDynamicSharedMemorySize, SMEM_BYTES);

    const dim3 gg(DMODEL / 128, NROWS / 128);   // (8, 64)
    gemm_mma<1><<<gg, 256>>>(query, Wq, bq, qp);
    gemm_mma<1><<<gg, 256>>>(key,   Wk, bk, kp);
    gemm_mma<1><<<gg, 256>>>(value, Wv, bv, vp);
    attn_kernel<<<dim3(TSEQ / 128, NBATCH * NHEADS), 256, SMEM_BYTES>>>(qp, kp, vp, cp);
    gemm_mma<0><<<gg, 256>>>(cp, Wo, bo, out);
}